// round 13
// baseline (speedup 1.0000x reference)
#include <cuda_runtime.h>
#include <cstdint>

#define Bv 64
#define Lv 512
#define Iv 256
#define Hv 512

#define CG 32
#define NBLK 64    // 32 col-groups x 2 slots; each CTA interleaves 2 batch groups
#define CPB 16
#define BPB 16
#define NT 256

#define PH 516     // pitch: 516 mod 32 == 4 -> conflict-free LDS.128

typedef unsigned long long ull;

// Global state, layout [b][k]
__device__ float g_h [Bv*Hv];
__device__ float g_m [Bv*Hv];
__device__ float g_k1[Bv*Hv];
__device__ float g_k2[Bv*Hv];
__device__ float g_k3[Bv*Hv];
__device__ float g_ho[Bv*Hv];
__device__ unsigned g_bar[4*32];

__device__ __forceinline__ void ffma2(ull& a, ull x, ull y){
    asm("fma.rn.f32x2 %0, %1, %2, %0;" : "+l"(a) : "l"(x), "l"(y));
}
__device__ __forceinline__ float lo32(ull v){ return __int_as_float((unsigned)v); }
__device__ __forceinline__ float hi32(ull v){ return __int_as_float((unsigned)(v>>32)); }
__device__ __forceinline__ float hsum1(ull a){ return lo32(a)+hi32(a); }
__device__ __forceinline__ float sigm(float v){ return 1.0f/(1.0f+expf(-v)); }

__device__ __forceinline__ void bar_arrive(unsigned* c){
    asm volatile("red.release.gpu.global.add.u32 [%0], 1;" :: "l"(c) : "memory");
}
__device__ __forceinline__ unsigned ld_acq(const unsigned* c){
    unsigned v;
    asm volatile("ld.acquire.gpu.global.u32 %0, [%1];" : "=r"(v) : "l"(c) : "memory");
    return v;
}

// K=256 slice GEMV: packed f32x2, 2 batches, 4 chains
__device__ __forceinline__ void gemv256(const float* __restrict__ w,
                                        const float* __restrict__ rE,
                                        const float* __restrict__ rO,
                                        float& sE, float& sO){
    const ulonglong2* __restrict__ w2 = (const ulonglong2*)w;
    const ulonglong2* __restrict__ e2 = (const ulonglong2*)rE;
    const ulonglong2* __restrict__ o2 = (const ulonglong2*)rO;
    ull aE0=0, aE1=0, aO0=0, aO1=0;
    #pragma unroll 16
    for (int j = 0; j < 64; j++){
        ulonglong2 wv = w2[j], e = e2[j], o = o2[j];
        ffma2(aE0, wv.x, e.x); ffma2(aE1, wv.y, e.y);
        ffma2(aO0, wv.x, o.x); ffma2(aO1, wv.y, o.y);
    }
    sE = hsum1(aE0) + hsum1(aE1);
    sO = hsum1(aO0) + hsum1(aO1);
}

__global__ void init_bar_kernel(){
    if (threadIdx.x < 4*32) g_bar[threadIdx.x] = 0;
}

__global__ void __launch_bounds__(NT, 1)
odegru_main(const float* __restrict__ x,     const float* __restrict__ tdel,
            const float* __restrict__ w_ih,  const float* __restrict__ w_hh,
            const float* __restrict__ b_ih,  const float* __restrict__ b_hh,
            const float* __restrict__ dw0,   const float* __restrict__ db0,
            const float* __restrict__ dw1,   const float* __restrict__ db1,
            const float* __restrict__ h0,    const int*   __restrict__ seq_lens,
            float* __restrict__ out){
    extern __shared__ float smem[];
    float* s_dw0 = smem;                    // 16*PH
    float* s_dw1 = s_dw0 + CPB*PH;
    float* s_whh = s_dw1 + CPB*PH;          // 3*16*PH
    float* s_inE = s_whh + 3*CPB*PH;        // 8*PH (shared by both groups, reused)
    float* s_inO = s_inE + 8*PH;            // 8*PH
    float* s_red = s_inO + 8*PH;            // 1024 floats = 512 float2

    const int blk = blockIdx.x;
    const int cg  = blk & 31;
    const int sl  = blk >> 5;               // slot 0: groups {0,1}; slot 1: {2,3}
    const int c0  = cg*CPB;
    const int tid = threadIdx.x;

    const int wid    = tid >> 5;            // 8 warps
    const int lane   = tid & 31;
    const int q      = wid & 3;             // col quad
    const int kh     = wid >> 2;            // K half 0/1
    const int colIdx = lane & 3;
    const int p      = lane >> 2;           // batch pair 0..7
    const int c_loc  = (q<<2) + colIdx;
    const int c      = c0 + c_loc;
    const int bE     = p<<1, bO = bE+1;
    const int kbase  = kh << 8;             // 0 or 256
    const int slot   = (q<<5) + lane;       // 0..127

    const int b0A = (sl*2)*BPB, b0B = (sl*2+1)*BPB;
    unsigned* ctrA = &g_bar[(sl*2)*32];
    unsigned* ctrB = &g_bar[(sl*2+1)*32];
    unsigned cntA = 0, cntB = 0, preA = 0, preB = 0;

    // persistent weight slices (float4, pitch PH)
    #pragma unroll
    for (int ii = 0; ii < 8; ii++){
        int item = tid + ii*NT;
        int r = item >> 7, k4 = (item & 127) << 2;
        *(float4*)&s_dw0[r*PH + k4] = *(const float4*)&dw0[(c0+r)*Hv + k4];
        *(float4*)&s_dw1[r*PH + k4] = *(const float4*)&dw1[(c0+r)*Hv + k4];
    }
    #pragma unroll
    for (int g = 0; g < 3; g++){
        #pragma unroll
        for (int ii = 0; ii < 8; ii++){
            int item = tid + ii*NT;
            int r = item >> 7, k4 = (item & 127) << 2;
            *(float4*)&s_whh[(g*CPB + r)*PH + k4] =
                *(const float4*)&w_hh[(g*Hv + c0 + r)*Hv + k4];
        }
    }

    const float db0c = db0[c], db1c = db1[c];
    const float bhr = b_hh[c], bhz = b_hh[Hv+c], bhn = b_hh[2*Hv+c];
    const float bir = b_ih[c], biz = b_ih[Hv+c], bin_ = b_ih[2*Hv+c];
    const int slenEA = seq_lens[b0A+bE], slenOA = seq_lens[b0A+bO];
    const int slenEB = seq_lens[b0B+bE], slenOB = seq_lens[b0B+bO];

    // init hidden state for both groups (own 16 cols)
    {
        int ty_i = tid >> 4, tx_i = tid & 15;
        float v = h0[c0+ty_i];
        __stcg(&g_h[(b0A+tx_i)*Hv + (c0+ty_i)], v);
        __stcg(&g_h[(b0B+tx_i)*Hv + (c0+ty_i)], v);
    }
    float hprEA = h0[c], hprOA = h0[c], hprEB = h0[c], hprOB = h0[c];

    __syncthreads();
    if (tid == 0){ bar_arrive(ctrA); bar_arrive(ctrB); }
    cntA = 1; cntB = 1;

    const float* wD0 = s_dw0 + c_loc*PH + kbase;
    const float* wD1 = s_dw1 + c_loc*PH + kbase;
    const float* inE = s_inE + p*PH + kbase;
    const float* inO = s_inO + p*PH + kbase;

    float k1EA=0,k1OA=0,k2EA=0,k2OA=0,k3EA=0,k3OA=0,hoEA=0,hoOA=0;
    float k1EB=0,k1OB=0,k2EB=0,k2OB=0,k3EB=0,k3OB=0,hoEB=0,hoOB=0;

    // ---- generic ODE stage: wait + prefetch-other + stage + gemv + reduce + epi + arrive
    auto odeStage = [&](const float* w, int b0, unsigned* ctrS, unsigned* ctrO,
                        unsigned& cntS, unsigned& preS, unsigned& preO,
                        auto ldr, auto epi){
        unsigned tgt = cntS*32;
        if (tid == 0 && preS < tgt){ while (ld_acq(ctrS) < tgt) { } }
        __syncthreads();
        if (tid == 0) preO = ld_acq(ctrO);   // prefetch other group's counter
        #pragma unroll
        for (int ii = 0; ii < 8; ii++){
            int item = tid + ii*NT;
            int bb = item >> 7, k4 = (item & 127) << 2;
            float4 v = ldr(b0, bb, k4);
            float* dst = ((bb & 1) ? s_inO : s_inE) + (bb >> 1)*PH + k4;
            *(float4*)dst = v;
        }
        __syncthreads();
        float vE, vO;
        gemv256(w, inE, inO, vE, vO);
        float2* R = (float2*)s_red;
        if (kh) R[slot] = make_float2(vE, vO);
        __syncthreads();
        if (!kh){ float2 o = R[slot]; epi(vE + o.x, vO + o.y); }
        __syncthreads();
        if (tid == 0) bar_arrive(ctrS);
        cntS++;
    };

    // shared loaders
    auto ldH  = [&](int b0,int bb,int k){ return __ldcg((const float4*)&g_h [(b0+bb)*Hv + k]); };
    auto ldM  = [&](int b0,int bb,int k){ return __ldcg((const float4*)&g_m [(b0+bb)*Hv + k]); };
    auto ldS3 = [&](int b0,int bb,int k){ int i=(b0+bb)*Hv+k;
        float4 h4=__ldcg((const float4*)&g_h[i]); float4 a4=__ldcg((const float4*)&g_k1[i]);
        return make_float4(fmaf(1.f/3.f,a4.x,h4.x), fmaf(1.f/3.f,a4.y,h4.y),
                           fmaf(1.f/3.f,a4.z,h4.z), fmaf(1.f/3.f,a4.w,h4.w)); };
    auto ldS5 = [&](int b0,int bb,int k){ int i=(b0+bb)*Hv+k;
        float4 h4=__ldcg((const float4*)&g_h[i]); float4 a4=__ldcg((const float4*)&g_k1[i]);
        float4 c4=__ldcg((const float4*)&g_k2[i]);
        return make_float4(h4.x+c4.x-(1.f/3.f)*a4.x, h4.y+c4.y-(1.f/3.f)*a4.y,
                           h4.z+c4.z-(1.f/3.f)*a4.z, h4.w+c4.w-(1.f/3.f)*a4.w); };
    auto ldS7 = [&](int b0,int bb,int k){ int i=(b0+bb)*Hv+k;
        float4 h4=__ldcg((const float4*)&g_h[i]); float4 a4=__ldcg((const float4*)&g_k1[i]);
        float4 c4=__ldcg((const float4*)&g_k2[i]); float4 d4=__ldcg((const float4*)&g_k3[i]);
        return make_float4(h4.x+a4.x-c4.x+d4.x, h4.y+a4.y-c4.y+d4.y,
                           h4.z+a4.z-c4.z+d4.z, h4.w+a4.w-c4.w+d4.w); };

    // S9 (GRU) stage, group-parameterized
    auto gruStage = [&](int t, int b0, unsigned* ctrS, unsigned* ctrO,
                        unsigned& cntS, unsigned& preS, unsigned& preO,
                        float actE_, float actO_, float& hprE_, float& hprO_,
                        float hoE_, float hoO_, int slenE_, int slenO_){
        unsigned tgt = cntS*32;
        if (tid == 0 && preS < tgt){ while (ld_acq(ctrS) < tgt) { } }
        __syncthreads();
        if (tid == 0) preO = ld_acq(ctrO);
        #pragma unroll
        for (int ii = 0; ii < 8; ii++){
            int item = tid + ii*NT;
            int bb = item >> 7, k4 = (item & 127) << 2;
            float4 v = __ldcg((const float4*)&g_ho[(b0+bb)*Hv + k4]);
            float* dst = ((bb & 1) ? s_inO : s_inE) + (bb >> 1)*PH + k4;
            *(float4*)dst = v;
        }
        __syncthreads();
        ull arE=0,arO=0,azE=0,azO=0,anE=0,anO=0;
        {
            const ulonglong2* __restrict__ e2 = (const ulonglong2*)inE;
            const ulonglong2* __restrict__ o2 = (const ulonglong2*)inO;
            const ulonglong2* __restrict__ r2 = (const ulonglong2*)(s_whh + c_loc*PH + kbase);
            const ulonglong2* __restrict__ z2 = (const ulonglong2*)(s_whh + (CPB + c_loc)*PH + kbase);
            const ulonglong2* __restrict__ n2 = (const ulonglong2*)(s_whh + (2*CPB + c_loc)*PH + kbase);
            #pragma unroll 8
            for (int j = 0; j < 64; j++){
                ulonglong2 e = e2[j], o = o2[j];
                ulonglong2 wr = r2[j], wz = z2[j], wn = n2[j];
                ffma2(arE, wr.x, e.x); ffma2(arE, wr.y, e.y);
                ffma2(arO, wr.x, o.x); ffma2(arO, wr.y, o.y);
                ffma2(azE, wz.x, e.x); ffma2(azE, wz.y, e.y);
                ffma2(azO, wz.x, o.x); ffma2(azO, wz.y, o.y);
                ffma2(anE, wn.x, e.x); ffma2(anE, wn.y, e.y);
                ffma2(anO, wn.x, o.x); ffma2(anO, wn.y, o.y);
            }
        }
        ull xrE=0,xrO=0,xzE=0,xzO=0,xnE=0,xnO=0;
        {
            const int kx = kh << 7;   // Iv=256 split in halves
            const float* xE = x + (size_t)(b0+bE)*(Lv*Iv) + (size_t)t*Iv + kx;
            const float* xO = x + (size_t)(b0+bO)*(Lv*Iv) + (size_t)t*Iv + kx;
            const ulonglong2* __restrict__ r2 = (const ulonglong2*)(w_ih + (size_t)c*Iv + kx);
            const ulonglong2* __restrict__ z2 = (const ulonglong2*)(w_ih + (size_t)(Hv + c)*Iv + kx);
            const ulonglong2* __restrict__ n2 = (const ulonglong2*)(w_ih + (size_t)(2*Hv + c)*Iv + kx);
            #pragma unroll 4
            for (int j = 0; j < 32; j++){
                float4 ef = __ldcg((const float4*)(xE + 4*j));
                float4 of = __ldcg((const float4*)(xO + 4*j));
                ulonglong2 e = *(ulonglong2*)&ef;
                ulonglong2 o = *(ulonglong2*)&of;
                ulonglong2 wr = r2[j], wz = z2[j], wn = n2[j];
                ffma2(xrE, wr.x, e.x); ffma2(xrE, wr.y, e.y);
                ffma2(xrO, wr.x, o.x); ffma2(xrO, wr.y, o.y);
                ffma2(xzE, wz.x, e.x); ffma2(xzE, wz.y, e.y);
                ffma2(xzO, wz.x, o.x); ffma2(xzO, wz.y, o.y);
                ffma2(xnE, wn.x, e.x); ffma2(xnE, wn.y, e.y);
                ffma2(xnO, wn.x, o.x); ffma2(xnO, wn.y, o.y);
            }
        }
        float prE = hsum1(arE) + actE_*hsum1(xrE);
        float prO = hsum1(arO) + actO_*hsum1(xrO);
        float pzE = hsum1(azE) + actE_*hsum1(xzE);
        float pzO = hsum1(azO) + actO_*hsum1(xzO);
        float pnE = hsum1(anE), pnO = hsum1(anO);
        float pxE = actE_*hsum1(xnE), pxO = actO_*hsum1(xnO);
        float2* R = (float2*)s_red;
        if (kh){
            R[        slot] = make_float2(prE, prO);
            R[128 +   slot] = make_float2(pzE, pzO);
            R[256 +   slot] = make_float2(pnE, pnO);
            R[384 +   slot] = make_float2(pxE, pxO);
        }
        __syncthreads();
        if (!kh){
            float2 a = R[slot], bq = R[128+slot], cc = R[256+slot], d = R[384+slot];
            float arT = prE + a.x,  arU = prO + a.y;
            float azT = pzE + bq.x, azU = pzO + bq.y;
            float anT = pnE + cc.x, anU = pnO + cc.y;
            float xnT = pxE + d.x,  xnU = pxO + d.y;
            float rE_ = sigm(arT + bir + bhr), rO_ = sigm(arU + bir + bhr);
            float zE_ = sigm(azT + biz + bhz), zO_ = sigm(azU + biz + bhz);
            float nE_ = tanhf(xnT + bin_ + rE_*(anT + bhn));
            float nO_ = tanhf(xnU + bin_ + rO_*(anU + bhn));
            float hnE = (1.f - zE_)*nE_ + zE_*hoE_;
            float hnO = (1.f - zO_)*nO_ + zO_*hoO_;
            __stcg(&g_h[(b0+bE)*Hv + c], hnE);
            __stcg(&g_h[(b0+bO)*Hv + c], hnO);
            out[(size_t)(b0+bE)*(Lv*Hv) + (size_t)t*Hv + c] = hnE;
            out[(size_t)(b0+bO)*(Lv*Hv) + (size_t)t*Hv + c] = hnO;
            if (t == slenE_ - 1) out[(size_t)Bv*Lv*Hv + (b0+bE)*Hv + c] = hnE;
            if (t == slenO_ - 1) out[(size_t)Bv*Lv*Hv + (b0+bO)*Hv + c] = hnO;
            hprE_ = hnE; hprO_ = hnO;
        }
        __syncthreads();
        if (tid == 0) bar_arrive(ctrS);
        cntS++;
    };

    for (int t = 0; t < Lv; t++){
        const float actEA = (t < slenEA) ? 1.0f : 0.0f;
        const float actOA = (t < slenOA) ? 1.0f : 0.0f;
        const float actEB = (t < slenEB) ? 1.0f : 0.0f;
        const float actOB = (t < slenOB) ? 1.0f : 0.0f;
        const float tdEA = actEA * __ldg(&tdel[(b0A+bE)*Lv + t]);
        const float tdOA = actOA * __ldg(&tdel[(b0A+bO)*Lv + t]);
        const float tdEB = actEB * __ldg(&tdel[(b0B+bE)*Lv + t]);
        const float tdOB = actOB * __ldg(&tdel[(b0B+bO)*Lv + t]);

        // S1
        odeStage(wD0, b0A, ctrA, ctrB, cntA, preA, preB, ldH, [&](float aE,float aO){
            __stcg(&g_m[(b0A+bE)*Hv + c], tanhf(aE + db0c));
            __stcg(&g_m[(b0A+bO)*Hv + c], tanhf(aO + db0c)); });
        odeStage(wD0, b0B, ctrB, ctrA, cntB, preB, preA, ldH, [&](float aE,float aO){
            __stcg(&g_m[(b0B+bE)*Hv + c], tanhf(aE + db0c));
            __stcg(&g_m[(b0B+bO)*Hv + c], tanhf(aO + db0c)); });
        // S2
        odeStage(wD1, b0A, ctrA, ctrB, cntA, preA, preB, ldM, [&](float aE,float aO){
            k1EA = tanhf(aE + db1c) * tdEA; k1OA = tanhf(aO + db1c) * tdOA;
            __stcg(&g_k1[(b0A+bE)*Hv + c], k1EA); __stcg(&g_k1[(b0A+bO)*Hv + c], k1OA); });
        odeStage(wD1, b0B, ctrB, ctrA, cntB, preB, preA, ldM, [&](float aE,float aO){
            k1EB = tanhf(aE + db1c) * tdEB; k1OB = tanhf(aO + db1c) * tdOB;
            __stcg(&g_k1[(b0B+bE)*Hv + c], k1EB); __stcg(&g_k1[(b0B+bO)*Hv + c], k1OB); });
        // S3
        odeStage(wD0, b0A, ctrA, ctrB, cntA, preA, preB, ldS3, [&](float aE,float aO){
            __stcg(&g_m[(b0A+bE)*Hv + c], tanhf(aE + db0c));
            __stcg(&g_m[(b0A+bO)*Hv + c], tanhf(aO + db0c)); });
        odeStage(wD0, b0B, ctrB, ctrA, cntB, preB, preA, ldS3, [&](float aE,float aO){
            __stcg(&g_m[(b0B+bE)*Hv + c], tanhf(aE + db0c));
            __stcg(&g_m[(b0B+bO)*Hv + c], tanhf(aO + db0c)); });
        // S4
        odeStage(wD1, b0A, ctrA, ctrB, cntA, preA, preB, ldM, [&](float aE,float aO){
            k2EA = tanhf(aE + db1c) * tdEA; k2OA = tanhf(aO + db1c) * tdOA;
            __stcg(&g_k2[(b0A+bE)*Hv + c], k2EA); __stcg(&g_k2[(b0A+bO)*Hv + c], k2OA); });
        odeStage(wD1, b0B, ctrB, ctrA, cntB, preB, preA, ldM, [&](float aE,float aO){
            k2EB = tanhf(aE + db1c) * tdEB; k2OB = tanhf(aO + db1c) * tdOB;
            __stcg(&g_k2[(b0B+bE)*Hv + c], k2EB); __stcg(&g_k2[(b0B+bO)*Hv + c], k2OB); });
        // S5
        odeStage(wD0, b0A, ctrA, ctrB, cntA, preA, preB, ldS5, [&](float aE,float aO){
            __stcg(&g_m[(b0A+bE)*Hv + c], tanhf(aE + db0c));
            __stcg(&g_m[(b0A+bO)*Hv + c], tanhf(aO + db0c)); });
        odeStage(wD0, b0B, ctrB, ctrA, cntB, preB, preA, ldS5, [&](float aE,float aO){
            __stcg(&g_m[(b0B+bE)*Hv + c], tanhf(aE + db0c));
            __stcg(&g_m[(b0B+bO)*Hv + c], tanhf(aO + db0c)); });
        // S6
        odeStage(wD1, b0A, ctrA, ctrB, cntA, preA, preB, ldM, [&](float aE,float aO){
            k3EA = tanhf(aE + db1c) * tdEA; k3OA = tanhf(aO + db1c) * tdOA;
            __stcg(&g_k3[(b0A+bE)*Hv + c], k3EA); __stcg(&g_k3[(b0A+bO)*Hv + c], k3OA); });
        odeStage(wD1, b0B, ctrB, ctrA, cntB, preB, preA, ldM, [&](float aE,float aO){
            k3EB = tanhf(aE + db1c) * tdEB; k3OB = tanhf(aO + db1c) * tdOB;
            __stcg(&g_k3[(b0B+bE)*Hv + c], k3EB); __stcg(&g_k3[(b0B+bO)*Hv + c], k3OB); });
        // S7
        odeStage(wD0, b0A, ctrA, ctrB, cntA, preA, preB, ldS7, [&](float aE,float aO){
            __stcg(&g_m[(b0A+bE)*Hv + c], tanhf(aE + db0c));
            __stcg(&g_m[(b0A+bO)*Hv + c], tanhf(aO + db0c)); });
        odeStage(wD0, b0B, ctrB, ctrA, cntB, preB, preA, ldS7, [&](float aE,float aO){
            __stcg(&g_m[(b0B+bE)*Hv + c], tanhf(aE + db0c));
            __stcg(&g_m[(b0B+bO)*Hv + c], tanhf(aO + db0c)); });
        // S8
        odeStage(wD1, b0A, ctrA, ctrB, cntA, preA, preB, ldM, [&](float aE,float aO){
            float k4E = tanhf(aE + db1c) * tdEA;
            float k4O = tanhf(aO + db1c) * tdOA;
            hoEA = hprEA + (k1EA + 3.f*(k2EA + k3EA) + k4E) * 0.125f;
            hoOA = hprOA + (k1OA + 3.f*(k2OA + k3OA) + k4O) * 0.125f;
            __stcg(&g_ho[(b0A+bE)*Hv + c], hoEA); __stcg(&g_ho[(b0A+bO)*Hv + c], hoOA); });
        odeStage(wD1, b0B, ctrB, ctrA, cntB, preB, preA, ldM, [&](float aE,float aO){
            float k4E = tanhf(aE + db1c) * tdEB;
            float k4O = tanhf(aO + db1c) * tdOB;
            hoEB = hprEB + (k1EB + 3.f*(k2EB + k3EB) + k4E) * 0.125f;
            hoOB = hprOB + (k1OB + 3.f*(k2OB + k3OB) + k4O) * 0.125f;
            __stcg(&g_ho[(b0B+bE)*Hv + c], hoEB); __stcg(&g_ho[(b0B+bO)*Hv + c], hoOB); });
        // S9
        gruStage(t, b0A, ctrA, ctrB, cntA, preA, preB, actEA, actOA,
                 hprEA, hprOA, hoEA, hoOA, slenEA, slenOA);
        gruStage(t, b0B, ctrB, ctrA, cntB, preB, preA, actEB, actOB,
                 hprEB, hprOB, hoEB, hoOB, slenEB, slenOB);
    }
}

extern "C" void kernel_launch(void* const* d_in, const int* in_sizes, int n_in,
                              void* d_out, int out_size){
    const float* x     = (const float*)d_in[0];
    const float* tdel  = (const float*)d_in[1];
    const float* w_ih  = (const float*)d_in[2];
    const float* w_hh  = (const float*)d_in[3];
    const float* b_ih  = (const float*)d_in[4];
    const float* b_hh  = (const float*)d_in[5];
    const float* dw0   = (const float*)d_in[6];
    const float* db0   = (const float*)d_in[7];
    const float* dw1   = (const float*)d_in[8];
    const float* db1   = (const float*)d_in[9];
    const float* h0    = (const float*)d_in[10];
    const int*   seq   = (const int*)d_in[11];
    float* out = (float*)d_out;

    // smem floats: 5*16*PH (weights) + 16*PH (inputs) + 1024 (reduce)
    size_t smem_floats = (size_t)(5*CPB*PH + 16*PH + 1024);
    size_t smem_bytes  = smem_floats * sizeof(float);   // 202,240 B
    cudaFuncSetAttribute(odegru_main, cudaFuncAttributeMaxDynamicSharedMemorySize,
                         (int)smem_bytes);

    init_bar_kernel<<<1, 128>>>();
    odegru_main<<<NBLK, NT, smem_bytes>>>(x, tdel, w_ih, w_hh, b_ih, b_hh,
                                          dw0, db0, dw1, db1, h0, seq, out);
}

// round 17
// speedup vs baseline: 1.9417x; 1.9417x over previous
#include <cuda_runtime.h>
#include <cstdint>

#define Bv 64
#define Lv 512
#define Iv 256
#define Hv 512

#define CG 32
#define RG 4
#define NBLK (CG*RG)
#define CPB 16
#define BPB 16
#define NT 512

#define PH 516     // pitch: 516 mod 32 == 4 -> conflict-free LDS.128

typedef unsigned long long ull;

// Global state, layout [b][k]; g_v holds the fused "next stage input"
__device__ float g_h[Bv*Hv];
__device__ float g_m[Bv*Hv];
__device__ float g_v[Bv*Hv];
__device__ unsigned g_bar[RG*32];

__device__ __forceinline__ void ffma2(ull& a, ull x, ull y){
    asm("fma.rn.f32x2 %0, %1, %2, %0;" : "+l"(a) : "l"(x), "l"(y));
}
__device__ __forceinline__ float lo32(ull v){ return __int_as_float((unsigned)v); }
__device__ __forceinline__ float hi32(ull v){ return __int_as_float((unsigned)(v>>32)); }
__device__ __forceinline__ float hsum1(ull a){ return lo32(a)+hi32(a); }
__device__ __forceinline__ float sigm(float v){ return 1.0f/(1.0f+expf(-v)); }

__device__ __forceinline__ void bar_arrive(unsigned* c){
    asm volatile("red.release.gpu.global.add.u32 [%0], 1;" :: "l"(c) : "memory");
}
__device__ __forceinline__ unsigned ld_rlx(const unsigned* c){
    unsigned v;
    asm volatile("ld.relaxed.gpu.global.u32 %0, [%1];" : "=r"(v) : "l"(c) : "memory");
    return v;
}
__device__ __forceinline__ unsigned ld_acq(const unsigned* c){
    unsigned v;
    asm volatile("ld.acquire.gpu.global.u32 %0, [%1];" : "=r"(v) : "l"(c) : "memory");
    return v;
}
// backoff barrier: relaxed poll + nanosleep, one acquire at the end
__device__ __forceinline__ void gbar(unsigned* ctr, unsigned target){
    __syncthreads();
    if (threadIdx.x == 0){
        bar_arrive(ctr);
        while (ld_rlx(ctr) < target) __nanosleep(64);
        (void)ld_acq(ctr);
    }
    __syncthreads();
}

__global__ void init_bar_kernel(){
    if (threadIdx.x < RG*32) g_bar[threadIdx.x] = 0;
}

__global__ void __launch_bounds__(NT, 1)
odegru_main(const float* __restrict__ x,     const float* __restrict__ tdel,
            const float* __restrict__ w_ih,  const float* __restrict__ w_hh,
            const float* __restrict__ b_ih,  const float* __restrict__ b_hh,
            const float* __restrict__ dw0,   const float* __restrict__ db0,
            const float* __restrict__ dw1,   const float* __restrict__ db1,
            const float* __restrict__ h0,    const int*   __restrict__ seq_lens,
            float* __restrict__ out){
    extern __shared__ float smem[];
    float* s_dw0 = smem;                    // 16*PH
    float* s_dw1 = s_dw0 + CPB*PH;
    float* s_whh = s_dw1 + CPB*PH;          // 3*16*PH
    float* s_inE = s_whh + 3*CPB*PH;        // 8*PH
    float* s_inO = s_inE + 8*PH;            // 8*PH
    float* s_red = s_inO + 8*PH;            // 3072 floats

    const int blk = blockIdx.x;
    const int cg  = blk & (CG-1);
    const int rg  = blk >> 5;
    const int c0  = cg*CPB, b0 = rg*BPB;
    const int tid = threadIdx.x;

    const int wid    = tid >> 5;
    const int lane   = tid & 31;
    const int q      = wid & 3;          // col quad
    const int kq     = wid >> 2;         // K quarter 0..3
    const int colIdx = lane & 3;
    const int p      = lane >> 2;        // batch pair 0..7
    const int c_loc  = (q<<2) + colIdx;
    const int c      = c0 + c_loc;
    const int bE     = p<<1, bO = bE+1;
    const int kbase  = kq << 7;          // 0,128,256,384
    const int slot   = q*32 + lane;      // 0..127

    // persistent weight slices (float4, pitch PH)
    #pragma unroll
    for (int ii = 0; ii < 4; ii++){
        int item = tid + ii*NT;
        int r = item >> 7, k4 = (item & 127) << 2;
        *(float4*)&s_dw0[r*PH + k4] = *(const float4*)&dw0[(c0+r)*Hv + k4];
        *(float4*)&s_dw1[r*PH + k4] = *(const float4*)&dw1[(c0+r)*Hv + k4];
    }
    #pragma unroll
    for (int g = 0; g < 3; g++){
        #pragma unroll
        for (int ii = 0; ii < 4; ii++){
            int item = tid + ii*NT;
            int r = item >> 7, k4 = (item & 127) << 2;
            *(float4*)&s_whh[(g*CPB + r)*PH + k4] =
                *(const float4*)&w_hh[(g*Hv + c0 + r)*Hv + k4];
        }
    }

    const float db0c = db0[c], db1c = db1[c];
    const float bhr = b_hh[c], bhz = b_hh[Hv+c], bhn = b_hh[2*Hv+c];
    const float bir = b_ih[c], biz = b_ih[Hv+c], bin_ = b_ih[2*Hv+c];
    const int slenE = seq_lens[b0+bE], slenO = seq_lens[b0+bO];

    // init hidden state (block owns its 16x16 tile)
    if (tid < 256){
        int ty_i = tid >> 4, tx_i = tid & 15;
        __stcg(&g_h[(b0+tx_i)*Hv + (c0+ty_i)], h0[c0+ty_i]);
    }
    float hprevE = h0[c], hprevO = h0[c];

    unsigned* ctr = &g_bar[rg*32];
    unsigned nbar = 0;

    const float* wD0 = s_dw0 + c_loc*PH + kbase;
    const float* wD1 = s_dw1 + c_loc*PH + kbase;
    const float* inE = s_inE + p*PH + kbase;
    const float* inO = s_inO + p*PH + kbase;

    float k1E=0.f,k1O=0.f,k2E=0.f,k2O=0.f,k3E=0.f,k3O=0.f,hoE=0.f,hoO=0.f;

    // stage: load ONE array, gemv, 4-way K reduce, epilogue on kq==0
    auto doStage = [&](const float* __restrict__ w, const float* __restrict__ gin,
                       auto epi){
        #pragma unroll
        for (int ii = 0; ii < 4; ii++){
            int item = tid + ii*NT;
            int bb = item >> 7, k4 = (item & 127) << 2;
            float4 v = __ldcg((const float4*)&gin[(b0+bb)*Hv + k4]);
            float* dst = ((bb & 1) ? s_inO : s_inE) + (bb >> 1)*PH + k4;
            *(float4*)dst = v;
        }
        __syncthreads();
        const ulonglong2* __restrict__ w2 = (const ulonglong2*)w;
        const ulonglong2* __restrict__ e2 = (const ulonglong2*)inE;
        const ulonglong2* __restrict__ o2 = (const ulonglong2*)inO;
        ull aE0=0, aE1=0, aO0=0, aO1=0;
        #pragma unroll
        for (int j = 0; j < 32; j++){
            ulonglong2 wv = w2[j], e = e2[j], o = o2[j];
            ffma2(aE0, wv.x, e.x); ffma2(aE1, wv.y, e.y);
            ffma2(aO0, wv.x, o.x); ffma2(aO1, wv.y, o.y);
        }
        float vE = hsum1(aE0) + hsum1(aE1);
        float vO = hsum1(aO0) + hsum1(aO1);
        float2* R = (float2*)s_red;
        if (kq) R[(kq-1)*128 + slot] = make_float2(vE, vO);
        __syncthreads();
        if (kq == 0){
            float2 p1 = R[slot], p2 = R[128+slot], p3 = R[256+slot];
            epi(vE + p1.x + p2.x + p3.x, vO + p1.y + p2.y + p3.y);
        }
    };

    for (int t = 0; t < Lv; t++){
        const float actE = (t < slenE) ? 1.0f : 0.0f;
        const float actO = (t < slenO) ? 1.0f : 0.0f;
        const float tdE = actE * __ldg(&tdel[(b0+bE)*Lv + t]);
        const float tdO = actO * __ldg(&tdel[(b0+bO)*Lv + t]);

        gbar(ctr, (++nbar)*32);              // publishes previous h (in g_h)

        // S1: m = tanh(h @ dw0^T + db0)
        doStage(wD0, g_h, [&](float aE,float aO){
            __stcg(&g_m[(b0+bE)*Hv + c], tanhf(aE + db0c));
            __stcg(&g_m[(b0+bO)*Hv + c], tanhf(aO + db0c)); });
        gbar(ctr, (++nbar)*32);
        // S2: k1 = tanh(m @ dw1^T + db1)*td ; publish v = h + k1/3
        doStage(wD1, g_m, [&](float aE,float aO){
            k1E = tanhf(aE + db1c) * tdE; k1O = tanhf(aO + db1c) * tdO;
            __stcg(&g_v[(b0+bE)*Hv + c], fmaf(1.f/3.f, k1E, hprevE));
            __stcg(&g_v[(b0+bO)*Hv + c], fmaf(1.f/3.f, k1O, hprevO)); });
        gbar(ctr, (++nbar)*32);
        // S3: m = tanh(v @ dw0^T + db0)
        doStage(wD0, g_v, [&](float aE,float aO){
            __stcg(&g_m[(b0+bE)*Hv + c], tanhf(aE + db0c));
            __stcg(&g_m[(b0+bO)*Hv + c], tanhf(aO + db0c)); });
        gbar(ctr, (++nbar)*32);
        // S4: k2 ; publish v = h + k2 - k1/3
        doStage(wD1, g_m, [&](float aE,float aO){
            k2E = tanhf(aE + db1c) * tdE; k2O = tanhf(aO + db1c) * tdO;
            __stcg(&g_v[(b0+bE)*Hv + c], hprevE + k2E - (1.f/3.f)*k1E);
            __stcg(&g_v[(b0+bO)*Hv + c], hprevO + k2O - (1.f/3.f)*k1O); });
        gbar(ctr, (++nbar)*32);
        // S5: m = tanh(v @ dw0^T + db0)
        doStage(wD0, g_v, [&](float aE,float aO){
            __stcg(&g_m[(b0+bE)*Hv + c], tanhf(aE + db0c));
            __stcg(&g_m[(b0+bO)*Hv + c], tanhf(aO + db0c)); });
        gbar(ctr, (++nbar)*32);
        // S6: k3 ; publish v = h + k1 - k2 + k3
        doStage(wD1, g_m, [&](float aE,float aO){
            k3E = tanhf(aE + db1c) * tdE; k3O = tanhf(aO + db1c) * tdO;
            __stcg(&g_v[(b0+bE)*Hv + c], hprevE + k1E - k2E + k3E);
            __stcg(&g_v[(b0+bO)*Hv + c], hprevO + k1O - k2O + k3O); });
        gbar(ctr, (++nbar)*32);
        // S7: m = tanh(v @ dw0^T + db0)
        doStage(wD0, g_v, [&](float aE,float aO){
            __stcg(&g_m[(b0+bE)*Hv + c], tanhf(aE + db0c));
            __stcg(&g_m[(b0+bO)*Hv + c], tanhf(aO + db0c)); });
        gbar(ctr, (++nbar)*32);
        // S8: k4 ; ho = h + (k1 + 3(k2+k3) + k4)/8 ; publish v = ho
        doStage(wD1, g_m, [&](float aE,float aO){
            float k4E = tanhf(aE + db1c) * tdE;
            float k4O = tanhf(aO + db1c) * tdO;
            hoE = hprevE + (k1E + 3.f*(k2E + k3E) + k4E) * 0.125f;
            hoO = hprevO + (k1O + 3.f*(k2O + k3O) + k4O) * 0.125f;
            __stcg(&g_v[(b0+bE)*Hv + c], hoE);
            __stcg(&g_v[(b0+bO)*Hv + c], hoO); });
        gbar(ctr, (++nbar)*32);
        // S9: GRU cell. h-part from smem (v=ho), x-part streamed from L2.
        {
            #pragma unroll
            for (int ii = 0; ii < 4; ii++){
                int item = tid + ii*NT;
                int bb = item >> 7, k4 = (item & 127) << 2;
                float4 v = __ldcg((const float4*)&g_v[(b0+bb)*Hv + k4]);
                float* dst = ((bb & 1) ? s_inO : s_inE) + (bb >> 1)*PH + k4;
                *(float4*)dst = v;
            }
            __syncthreads();
            ull arE=0,arO=0,azE=0,azO=0,anE=0,anO=0;
            {
                const ulonglong2* __restrict__ e2 = (const ulonglong2*)inE;
                const ulonglong2* __restrict__ o2 = (const ulonglong2*)inO;
                const ulonglong2* __restrict__ r2 = (const ulonglong2*)(s_whh + c_loc*PH + kbase);
                const ulonglong2* __restrict__ z2 = (const ulonglong2*)(s_whh + (CPB + c_loc)*PH + kbase);
                const ulonglong2* __restrict__ n2 = (const ulonglong2*)(s_whh + (2*CPB + c_loc)*PH + kbase);
                #pragma unroll 8
                for (int j = 0; j < 32; j++){
                    ulonglong2 e = e2[j], o = o2[j];
                    ulonglong2 wr = r2[j], wz = z2[j], wn = n2[j];
                    ffma2(arE, wr.x, e.x); ffma2(arE, wr.y, e.y);
                    ffma2(arO, wr.x, o.x); ffma2(arO, wr.y, o.y);
                    ffma2(azE, wz.x, e.x); ffma2(azE, wz.y, e.y);
                    ffma2(azO, wz.x, o.x); ffma2(azO, wz.y, o.y);
                    ffma2(anE, wn.x, e.x); ffma2(anE, wn.y, e.y);
                    ffma2(anO, wn.x, o.x); ffma2(anO, wn.y, o.y);
                }
            }
            ull xrE=0,xrO=0,xzE=0,xzO=0,xnE=0,xnO=0;
            {
                const int kx = kq << 6;   // Iv=256 in quarters
                const float* xE = x + (size_t)(b0+bE)*(Lv*Iv) + (size_t)t*Iv + kx;
                const float* xO = x + (size_t)(b0+bO)*(Lv*Iv) + (size_t)t*Iv + kx;
                const ulonglong2* __restrict__ r2 = (const ulonglong2*)(w_ih + (size_t)c*Iv + kx);
                const ulonglong2* __restrict__ z2 = (const ulonglong2*)(w_ih + (size_t)(Hv + c)*Iv + kx);
                const ulonglong2* __restrict__ n2 = (const ulonglong2*)(w_ih + (size_t)(2*Hv + c)*Iv + kx);
                #pragma unroll 4
                for (int j = 0; j < 16; j++){
                    float4 ef = __ldcg((const float4*)(xE + 4*j));
                    float4 of = __ldcg((const float4*)(xO + 4*j));
                    ulonglong2 e = *(ulonglong2*)&ef;
                    ulonglong2 o = *(ulonglong2*)&of;
                    ulonglong2 wr = r2[j], wz = z2[j], wn = n2[j];
                    ffma2(xrE, wr.x, e.x); ffma2(xrE, wr.y, e.y);
                    ffma2(xrO, wr.x, o.x); ffma2(xrO, wr.y, o.y);
                    ffma2(xzE, wz.x, e.x); ffma2(xzE, wz.y, e.y);
                    ffma2(xzO, wz.x, o.x); ffma2(xzO, wz.y, o.y);
                    ffma2(xnE, wn.x, e.x); ffma2(xnE, wn.y, e.y);
                    ffma2(xnO, wn.x, o.x); ffma2(xnO, wn.y, o.y);
                }
            }
            float prE = hsum1(arE) + actE*hsum1(xrE);
            float prO = hsum1(arO) + actO*hsum1(xrO);
            float pzE = hsum1(azE) + actE*hsum1(xzE);
            float pzO = hsum1(azO) + actO*hsum1(xzO);
            float pnE = hsum1(anE), pnO = hsum1(anO);
            float pxE = actE*hsum1(xnE), pxO = actO*hsum1(xnO);
            float2* R = (float2*)s_red;
            if (kq){
                int off = (kq-1)*512;
                R[off +        slot] = make_float2(prE, prO);
                R[off + 128 +  slot] = make_float2(pzE, pzO);
                R[off + 256 +  slot] = make_float2(pnE, pnO);
                R[off + 384 +  slot] = make_float2(pxE, pxO);
            }
            __syncthreads();
            if (kq == 0){
                float arT=prE, arU=prO, azT=pzE, azU=pzO, anT=pnE, anU=pnO, xnT=pxE, xnU=pxO;
                #pragma unroll
                for (int h = 0; h < 3; h++){
                    float2 a = R[h*512 +        slot]; arT += a.x; arU += a.y;
                    float2 bq= R[h*512 + 128 +  slot]; azT += bq.x; azU += bq.y;
                    float2 cc= R[h*512 + 256 +  slot]; anT += cc.x; anU += cc.y;
                    float2 d = R[h*512 + 384 +  slot]; xnT += d.x; xnU += d.y;
                }
                float rE_ = sigm(arT + bir + bhr), rO_ = sigm(arU + bir + bhr);
                float zE_ = sigm(azT + biz + bhz), zO_ = sigm(azU + biz + bhz);
                float nE_ = tanhf(xnT + bin_ + rE_*(anT + bhn));
                float nO_ = tanhf(xnU + bin_ + rO_*(anU + bhn));
                float hnE = (1.f - zE_)*nE_ + zE_*hoE;
                float hnO = (1.f - zO_)*nO_ + zO_*hoO;
                __stcg(&g_h[(b0+bE)*Hv + c], hnE);
                __stcg(&g_h[(b0+bO)*Hv + c], hnO);
                out[(size_t)(b0+bE)*(Lv*Hv) + (size_t)t*Hv + c] = hnE;
                out[(size_t)(b0+bO)*(Lv*Hv) + (size_t)t*Hv + c] = hnO;
                if (t == slenE - 1) out[(size_t)Bv*Lv*Hv + (b0+bE)*Hv + c] = hnE;
                if (t == slenO - 1) out[(size_t)Bv*Lv*Hv + (b0+bO)*Hv + c] = hnO;
                hprevE = hnE; hprevO = hnO;
            }
        }
        // loop-top gbar publishes g_h for the next step
    }
}

extern "C" void kernel_launch(void* const* d_in, const int* in_sizes, int n_in,
                              void* d_out, int out_size){
    const float* x     = (const float*)d_in[0];
    const float* tdel  = (const float*)d_in[1];
    const float* w_ih  = (const float*)d_in[2];
    const float* w_hh  = (const float*)d_in[3];
    const float* b_ih  = (const float*)d_in[4];
    const float* b_hh  = (const float*)d_in[5];
    const float* dw0   = (const float*)d_in[6];
    const float* db0   = (const float*)d_in[7];
    const float* dw1   = (const float*)d_in[8];
    const float* db1   = (const float*)d_in[9];
    const float* h0    = (const float*)d_in[10];
    const int*   seq   = (const int*)d_in[11];
    float* out = (float*)d_out;

    size_t smem_floats = (size_t)(5*CPB*PH + 16*PH + 3072);
    size_t smem_bytes  = smem_floats * sizeof(float);   // 210,432 B
    cudaFuncSetAttribute(odegru_main, cudaFuncAttributeMaxDynamicSharedMemorySize,
                         (int)smem_bytes);

    init_bar_kernel<<<1, 128>>>();
    odegru_main<<<NBLK, NT, smem_bytes>>>(x, tdel, w_ih, w_hh, b_ih, b_hh,
                                          dw0, db0, dw1, db1, h0, seq, out);
}